// round 15
// baseline (speedup 1.0000x reference)
#include <cuda_runtime.h>
#include <cuda_fp16.h>

#define Bsz 4
#define S   2048
#define D   128
#define H   8
#define DK  16
#define BH  (Bsz*H)
#define NQT (S/64)

typedef unsigned long long u64;
typedef unsigned int u32;

// 0.25 * log2(e): folded into Q at projection time so attention uses raw ex2
#define SCQ 0.36067376022224086f

// ---- scratch (no device allocations allowed) ----
__device__ float g_Q[BH*S*DK];                // pre-scaled by SCQ
__device__ float g_K[BH*S*DK];
__device__ float g_V[BH*S*DK];
__device__ float g_Vp[BH*S*DK];               // V / colsum (fp32, [m][v])
__device__ __half g_E[(size_t)BH*S*S];        // 256 MB, [bh][m][q], per-column biased
__device__ float g_colpart[NQT*BH*S];         // per-64q-tile colsum partials (8 MB)
__device__ float g_maxqn[BH];                 // max ||Qhat|| per head
__device__ float g_head[Bsz*S*D];

// ---- packed fp32x2 helpers ----
__device__ __forceinline__ void ffma2(u64& d, u64 a, u64 b){
    asm("fma.rn.f32x2 %0, %1, %2, %0;" : "+l"(d) : "l"(a), "l"(b));
}
__device__ __forceinline__ u64 add2(u64 a, u64 b){
    u64 r; asm("add.rn.f32x2 %0, %1, %2;" : "=l"(r) : "l"(a), "l"(b)); return r;
}
__device__ __forceinline__ u64 pack2(float lo, float hi){
    u64 r; asm("mov.b64 %0, {%1, %2};" : "=l"(r) : "f"(lo), "f"(hi)); return r;
}
__device__ __forceinline__ u64 dup2(float x){
    u64 r; asm("mov.b64 %0, {%1, %1};" : "=l"(r) : "f"(x)); return r;
}
__device__ __forceinline__ float hsum2(u64 v){
    float lo, hi; asm("mov.b64 {%0, %1}, %2;" : "=f"(lo), "=f"(hi) : "l"(v));
    return lo + hi;
}
__device__ __forceinline__ float2 unpk(u64 v){
    float2 r; asm("mov.b64 {%0, %1}, %2;" : "=f"(r.x), "=f"(r.y) : "l"(v));
    return r;
}
__device__ __forceinline__ float ex2f(float x){
    float r; asm("ex2.approx.f32 %0, %1;" : "=f"(r) : "f"(x)); return r;
}
__device__ __forceinline__ u64 lds64(const float* p){
    return *reinterpret_cast<const u64*>(p);
}
__device__ __forceinline__ u64 ldg64(const float* p){
    return *reinterpret_cast<const u64*>(p);
}

// ============================================================
// Kernel 1: Q/K/V projections. grid (B*S/64, 3), 128 threads.
// ============================================================
__global__ void proj_kernel(const float* __restrict__ x,
                            const float* __restrict__ wq,
                            const float* __restrict__ wk,
                            const float* __restrict__ wv) {
    __shared__ float xs[64][132];
    __shared__ float wsT[16][132];
    const int t = threadIdx.x;       // 128
    const int row0 = blockIdx.x * 64;
    const int pj = blockIdx.y;
    const float* W0 = (pj == 0 ? wq : pj == 1 ? wk : wv);
    float* dst = (pj == 0 ? g_Q : pj == 1 ? g_K : g_V);
    const float oscale = (pj == 0) ? SCQ : 1.0f;

    #pragma unroll
    for (int k = 0; k < 16; k++) {
        int idx = t + k*128;
        int r = idx >> 5, q4 = idx & 31;
        *reinterpret_cast<float4*>(&xs[r][q4*4]) =
            *reinterpret_cast<const float4*>(x + (row0 + r)*D + q4*4);
    }

    const int rg = t >> 3, cg = t & 7;
    for (int h = 0; h < H; h++) {
        __syncthreads();
        #pragma unroll
        for (int k = 0; k < 4; k++) {
            int idx = t + k*128;
            int d = idx >> 2, c4 = idx & 3;
            float4 v = *reinterpret_cast<const float4*>(W0 + h*D*DK + d*DK + c4*4);
            wsT[c4*4+0][d] = v.x; wsT[c4*4+1][d] = v.y;
            wsT[c4*4+2][d] = v.z; wsT[c4*4+3][d] = v.w;
        }
        __syncthreads();

        u64 acc[4][2] = {};
        #pragma unroll 8
        for (int d = 0; d < D; d += 2) {
            u64 w0 = lds64(&wsT[cg][d]);
            u64 w1 = lds64(&wsT[cg+8][d]);
            #pragma unroll
            for (int i = 0; i < 4; i++) {
                u64 xv = lds64(&xs[rg*4+i][d]);
                ffma2(acc[i][0], xv, w0);
                ffma2(acc[i][1], xv, w1);
            }
        }
        #pragma unroll
        for (int i = 0; i < 4; i++) {
            int grow = row0 + rg*4 + i;
            int b = grow >> 11, s = grow & (S-1);
            float* o = dst + ((b*H + h)*S + s)*DK;
            o[cg]   = hsum2(acc[i][0]) * oscale;
            o[cg+8] = hsum2(acc[i][1]) * oscale;
        }
    }
}

// ============================================================
// Kernel 1b: maxQnorm[bh] = max_q ||Qhat[q]||. grid BH, 256 threads.
// ============================================================
__global__ void __launch_bounds__(256) qnorm_kernel() {
    __shared__ float red[256];
    const int bh = blockIdx.x, t = threadIdx.x;
    const float* Qb = g_Q + bh*S*DK;
    float mx = 0.f;
    for (int r = t; r < S; r += 256) {
        u64 a = 0;
        #pragma unroll
        for (int j = 0; j < 8; j++) {
            u64 q = ldg64(Qb + r*DK + 2*j);
            ffma2(a, q, q);
        }
        mx = fmaxf(mx, hsum2(a));
    }
    red[t] = mx;
    __syncthreads();
    #pragma unroll
    for (int s2 = 128; s2; s2 >>= 1) {
        if (t < s2) red[t] = fmaxf(red[t], red[t + s2]);
        __syncthreads();
    }
    if (t == 0) g_maxqn[bh] = sqrtf(red[0]);
}

// ============================================================
// Kernel 2: E[m][q] = 2^(Qhat[q].K[m] - b_m) fp16 with CS bias
// b_m = maxQn*||K[m]|| - 8 (overflow impossible) + butterfly colparts.
// grid (S/128, BH), 256 threads (8 warps). Warps 0-3 own q[0,64) of
// the 128-q tile, warps 4-7 own q[64,128); both share one staged
// K-chunk; within a group warps split the 128-m chunk 4 ways.
// ============================================================
__global__ void __launch_bounds__(256) scoresE_kernel() {
    __shared__ float Ks[128][16];
    __shared__ float bs[128];
    const int t = threadIdx.x, w = t >> 5, lane = t & 31;
    const int grp = w >> 2, wm = w & 3;
    const int bh = blockIdx.y;
    const int q0 = blockIdx.x*128 + grp*64;
    const float* Qb = g_Q + bh*S*DK;
    const float* Kb = g_K + bh*S*DK;
    __half* Eb = g_E + (size_t)bh*S*S;
    float* cp = g_colpart + (blockIdx.x*2 + grp)*(BH*S) + bh*S;
    const float mq = g_maxqn[bh];

    u64 qa[8], qc[8];
    #pragma unroll
    for (int j = 0; j < 8; j++) {
        qa[j] = ldg64(Qb + (q0 + 2*lane)*DK + 2*j);
        qc[j] = ldg64(Qb + (q0 + 2*lane + 1)*DK + 2*j);
    }

    for (int m0 = 0; m0 < S; m0 += 128) {
        __syncthreads();                       // Ks/bs reuse
        #pragma unroll
        for (int i = 0; i < 2; i++) {
            int idx = t + i*256;               // 512 float4s
            int r = idx >> 2, c4 = idx & 3;
            *reinterpret_cast<float4*>(&Ks[r][c4*4]) =
                *reinterpret_cast<const float4*>(Kb + (m0 + r)*DK + c4*4);
        }
        __syncthreads();
        if (t < 128) {                         // per-row CS bias
            const ulonglong2* kp = reinterpret_cast<const ulonglong2*>(&Ks[t][0]);
            u64 a = 0;
            #pragma unroll
            for (int p = 0; p < 4; p++) {
                ulonglong2 kv = kp[p];
                ffma2(a, kv.x, kv.x);
                ffma2(a, kv.y, kv.y);
            }
            bs[t] = fmaf(sqrtf(hsum2(a)), mq, -8.0f);
        }
        __syncthreads();

        const int mbase = wm * 32;
        #pragma unroll 4
        for (int mi = 0; mi < 32; mi++) {
            const int m  = mbase + mi;
            const int mg = m0 + m;
            const u64 bias = pack2(-bs[m], 0.0f);
            const ulonglong2* kp = reinterpret_cast<const ulonglong2*>(&Ks[m][0]);
            u64 a0 = bias, a1 = 0, a2 = bias, a3 = 0;
            #pragma unroll
            for (int p = 0; p < 4; p++) {
                ulonglong2 kv = kp[p];               // LDS.128 broadcast
                ffma2(a0, qa[2*p],   kv.x);
                ffma2(a1, qa[2*p+1], kv.y);
                ffma2(a2, qc[2*p],   kv.x);
                ffma2(a3, qc[2*p+1], kv.y);
            }
            float e0 = fminf(ex2f(hsum2(add2(a0, a1))), 65472.0f);
            float e1 = fminf(ex2f(hsum2(add2(a2, a3))), 65472.0f);
            *reinterpret_cast<__half2*>(Eb + (size_t)mg*S + q0 + 2*lane) =
                __floats2half2_rn(e0, e1);           // coalesced 128B/warp
            // partial colsum over this group's 64 q's
            float cs = e0 + e1;
            #pragma unroll
            for (int off = 16; off; off >>= 1)
                cs += __shfl_xor_sync(0xffffffffu, cs, off);
            if (lane == 0) cp[mg] = cs;
        }
    }
}

// ============================================================
// Kernel 2b: reduce colsum partials -> Vp = V / colsum (fp32 rows).
// grid BH*S/256, 256 threads, 1 m-row each. ~12 MB total traffic.
// ============================================================
__global__ void __launch_bounds__(256) colredVp_kernel() {
    const int row = blockIdx.x*256 + threadIdx.x;   // bh*S + m
    float s = 0.f;
    #pragma unroll
    for (int qt = 0; qt < NQT; qt++) s += g_colpart[qt*(BH*S) + row];
    const float rc = (s > 0.f) ? __frcp_rn(s) : 0.f;
    const float4* Vr = reinterpret_cast<const float4*>(g_V + row*DK);
    float4* Op = reinterpret_cast<float4*>(g_Vp + row*DK);
    #pragma unroll
    for (int v4 = 0; v4 < 4; v4++) {
        float4 v = Vr[v4];
        v.x *= rc; v.y *= rc; v.z *= rc; v.w *= rc;
        Op[v4] = v;
    }
}

// ============================================================
// Kernel 3: out[q,:] = sum_m E[m][q] * Vp[m,:]. Scalar FFMA2 form
// (R5-proven) at 256 threads: lane owns q-pair of the 64-q tile,
// 8 warps split each 256-m chunk; Vp staged in SMEM (LDS.128
// broadcast); 7-slab cross-warp reduction at the end.
// red rows padded to 18 floats (72B): float2 stores stay 8B-aligned.
// grid (S/64, BH).
// ============================================================
__global__ void __launch_bounds__(256) ev_kernel() {
    __shared__ float Vs[256][16];              // 16 KB
    __shared__ float red[7][64][18];           // 31.5 KB, rows 72B (8B-aligned)
    const int t = threadIdx.x, w = t >> 5, lane = t & 31;
    const int bh = blockIdx.y;
    const int q0 = blockIdx.x * 64;
    const float* Vp = g_Vp + bh*S*DK;
    const __half* Eb = g_E + (size_t)bh*S*S;

    u64 acc0[8] = {}, acc1[8] = {};

    for (int m0 = 0; m0 < S; m0 += 256) {
        __syncthreads();
        #pragma unroll
        for (int i = 0; i < 4; i++) {
            int idx = t + i*256;               // 1024 float4s
            int r = idx >> 2, c4 = idx & 3;
            *reinterpret_cast<float4*>(&Vs[r][c4*4]) =
                *reinterpret_cast<const float4*>(Vp + (m0 + r)*DK + c4*4);
        }
        __syncthreads();

        const int mbase = w * 32;
        #pragma unroll 4
        for (int mi = 0; mi < 32; mi++) {
            const int m  = mbase + mi;
            const int mg = m0 + m;
            __half2 eh = *reinterpret_cast<const __half2*>(
                Eb + (size_t)mg*S + q0 + 2*lane);      // coalesced 128B/warp
            float2 ef = __half22float2(eh);
            u64 E0 = dup2(ef.x), E1 = dup2(ef.y);
            const ulonglong2* vp = reinterpret_cast<const ulonglong2*>(&Vs[m][0]);
            #pragma unroll
            for (int p = 0; p < 4; p++) {
                ulonglong2 vv = vp[p];                 // LDS.128 broadcast
                ffma2(acc0[2*p],   E0, vv.x);
                ffma2(acc0[2*p+1], E0, vv.y);
                ffma2(acc1[2*p],   E1, vv.x);
                ffma2(acc1[2*p+1], E1, vv.y);
            }
        }
    }

    // cross-warp reduction over the 8 m-slices
    __syncthreads();
    if (w) {
        #pragma unroll
        for (int j = 0; j < 8; j++) {
            float2 p0 = unpk(acc0[j]), p1 = unpk(acc1[j]);
            *reinterpret_cast<float2*>(&red[w-1][2*lane][2*j])   = p0;
            *reinterpret_cast<float2*>(&red[w-1][2*lane+1][2*j]) = p1;
        }
    }
    __syncthreads();
    if (w == 0) {
        const int b = bh >> 3, h = bh & 7;
        float o0[16], o1[16];
        #pragma unroll
        for (int j = 0; j < 8; j++) {
            float2 p0 = unpk(acc0[j]), p1 = unpk(acc1[j]);
            o0[2*j] = p0.x; o0[2*j+1] = p0.y;
            o1[2*j] = p1.x; o1[2*j+1] = p1.y;
        }
        #pragma unroll
        for (int sl = 0; sl < 7; sl++)
            #pragma unroll
            for (int c = 0; c < 16; c++) {
                o0[c] += red[sl][2*lane][c];
                o1[c] += red[sl][2*lane+1][c];
            }
        float* d0 = g_head + (b*S + q0 + 2*lane)*D     + h*DK;
        float* d1 = g_head + (b*S + q0 + 2*lane + 1)*D + h*DK;
        #pragma unroll
        for (int c4 = 0; c4 < 4; c4++) {
            *reinterpret_cast<float4*>(d0 + c4*4) =
                make_float4(o0[c4*4], o0[c4*4+1], o0[c4*4+2], o0[c4*4+3]);
            *reinterpret_cast<float4*>(d1 + c4*4) =
                make_float4(o1[c4*4], o1[c4*4+1], o1[c4*4+2], o1[c4*4+3]);
        }
    }
}

// ============================================================
// Kernel 4: out = head[B*S,128] @ w_o[128,128]. grid 256, 256 thr.
// ============================================================
__global__ void final_proj_kernel(const float* __restrict__ wo,
                                  float* __restrict__ out) {
    __shared__ float hsT[128][34];
    const int t = threadIdx.x;
    const int row0 = blockIdx.x * 32;

    #pragma unroll
    for (int k = 0; k < 4; k++) {
        int idx = t + k*256;
        int r = idx >> 5, j4 = idx & 31;
        float4 v = *reinterpret_cast<const float4*>(g_head + (row0 + r)*D + j4*4);
        hsT[j4*4+0][r] = v.x; hsT[j4*4+1][r] = v.y;
        hsT[j4*4+2][r] = v.z; hsT[j4*4+3][r] = v.w;
    }
    __syncthreads();

    const int c = t & 127, rh = t >> 7;
    u64 acc[8] = {};
    #pragma unroll 4
    for (int j = 0; j < D; j++) {
        u64 w = dup2(wo[j*D + c]);
        #pragma unroll
        for (int p = 0; p < 8; p++)
            ffma2(acc[p], lds64(&hsT[j][rh*16 + 2*p]), w);
    }
    #pragma unroll
    for (int p = 0; p < 8; p++) {
        float2 v = unpk(acc[p]);
        int r = row0 + rh*16 + 2*p;
        out[r*D + c]     = v.x;
        out[(r+1)*D + c] = v.y;
    }
}

// ============================================================
extern "C" void kernel_launch(void* const* d_in, const int* in_sizes, int n_in,
                              void* d_out, int out_size) {
    const float* x  = (const float*)d_in[0];
    const float* wq = (const float*)d_in[1];
    const float* wk = (const float*)d_in[2];
    const float* wv = (const float*)d_in[3];
    const float* wo = (const float*)d_in[4];
    float* out = (float*)d_out;

    proj_kernel      <<< dim3(Bsz*S/64, 3), 128 >>>(x, wq, wk, wv);
    qnorm_kernel     <<< BH,                256 >>>();
    scoresE_kernel   <<< dim3(S/128, BH),   256 >>>();
    colredVp_kernel  <<< BH*S/256,          256 >>>();
    ev_kernel        <<< dim3(S/64, BH),    256 >>>();
    final_proj_kernel<<< Bsz*S/32,          256 >>>(wo, out);
}

// round 16
// speedup vs baseline: 1.3373x; 1.3373x over previous
#include <cuda_runtime.h>
#include <cuda_fp16.h>

#define Bsz 4
#define S   2048
#define D   128
#define H   8
#define DK  16
#define BH  (Bsz*H)
#define NSL 128            // colpart sub-slabs (16-q granularity)

typedef unsigned long long u64;
typedef unsigned int u32;

// 0.25 * log2(e): folded into Q at projection time so attention uses raw ex2
#define SCQ 0.36067376022224086f

// ---- scratch (no device allocations allowed) ----
__device__ float g_Q[BH*S*DK];                // pre-scaled by SCQ (fp32)
__device__ float g_K[BH*S*DK];
__device__ float g_V[BH*S*DK];
__device__ float g_Vp[BH*S*DK];               // V / colsum (fp32)
__device__ __half g_QhT[BH*DK*S];             // Qhat fp16, [bh][k][q] (2 MB)
__device__ __half g_Kh[BH*S*DK];              // K fp16, [bh][m][k] (2 MB)
__device__ float g_negb[BH*S];                // 8 - maxQn*||K[m]|| (neg CS bias)
__device__ __half g_E[(size_t)BH*S*S];        // 256 MB, [bh][m][q]
__device__ float g_colpart[NSL*BH*S];         // per-16q colsum partials (33.5 MB)
__device__ float g_maxqn[BH];
__device__ float g_head[Bsz*S*D];

// ---- packed fp32x2 helpers ----
__device__ __forceinline__ void ffma2(u64& d, u64 a, u64 b){
    asm("fma.rn.f32x2 %0, %1, %2, %0;" : "+l"(d) : "l"(a), "l"(b));
}
__device__ __forceinline__ u64 dup2(float x){
    u64 r; asm("mov.b64 %0, {%1, %1};" : "=l"(r) : "f"(x)); return r;
}
__device__ __forceinline__ float hsum2(u64 v){
    float lo, hi; asm("mov.b64 {%0, %1}, %2;" : "=f"(lo), "=f"(hi) : "l"(v));
    return lo + hi;
}
__device__ __forceinline__ float2 unpk(u64 v){
    float2 r; asm("mov.b64 {%0, %1}, %2;" : "=f"(r.x), "=f"(r.y) : "l"(v));
    return r;
}
__device__ __forceinline__ float ex2f(float x){
    float r; asm("ex2.approx.f32 %0, %1;" : "=f"(r) : "f"(x)); return r;
}
__device__ __forceinline__ u64 lds64(const float* p){
    return *reinterpret_cast<const u64*>(p);
}
__device__ __forceinline__ u64 ldg64(const float* p){
    return *reinterpret_cast<const u64*>(p);
}
__device__ __forceinline__ u32 smem_u32(const void* p){
    u32 a;
    asm("{ .reg .u64 t; cvta.to.shared.u64 t, %1; cvt.u32.u64 %0, t; }"
        : "=r"(a) : "l"(p));
    return a;
}

// ============================================================
// Kernel 1: Q/K/V projections. grid (B*S/64, 3), 128 threads.
// ============================================================
__global__ void proj_kernel(const float* __restrict__ x,
                            const float* __restrict__ wq,
                            const float* __restrict__ wk,
                            const float* __restrict__ wv) {
    __shared__ float xs[64][132];
    __shared__ float wsT[16][132];
    const int t = threadIdx.x;       // 128
    const int row0 = blockIdx.x * 64;
    const int pj = blockIdx.y;
    const float* W0 = (pj == 0 ? wq : pj == 1 ? wk : wv);
    float* dst = (pj == 0 ? g_Q : pj == 1 ? g_K : g_V);
    const float oscale = (pj == 0) ? SCQ : 1.0f;

    #pragma unroll
    for (int k = 0; k < 16; k++) {
        int idx = t + k*128;
        int r = idx >> 5, q4 = idx & 31;
        *reinterpret_cast<float4*>(&xs[r][q4*4]) =
            *reinterpret_cast<const float4*>(x + (row0 + r)*D + q4*4);
    }

    const int rg = t >> 3, cg = t & 7;
    for (int h = 0; h < H; h++) {
        __syncthreads();
        #pragma unroll
        for (int k = 0; k < 4; k++) {
            int idx = t + k*128;
            int d = idx >> 2, c4 = idx & 3;
            float4 v = *reinterpret_cast<const float4*>(W0 + h*D*DK + d*DK + c4*4);
            wsT[c4*4+0][d] = v.x; wsT[c4*4+1][d] = v.y;
            wsT[c4*4+2][d] = v.z; wsT[c4*4+3][d] = v.w;
        }
        __syncthreads();

        u64 acc[4][2] = {};
        #pragma unroll 8
        for (int d = 0; d < D; d += 2) {
            u64 w0 = lds64(&wsT[cg][d]);
            u64 w1 = lds64(&wsT[cg+8][d]);
            #pragma unroll
            for (int i = 0; i < 4; i++) {
                u64 xv = lds64(&xs[rg*4+i][d]);
                ffma2(acc[i][0], xv, w0);
                ffma2(acc[i][1], xv, w1);
            }
        }
        #pragma unroll
        for (int i = 0; i < 4; i++) {
            int grow = row0 + rg*4 + i;
            int b = grow >> 11, s = grow & (S-1);
            float* o = dst + ((b*H + h)*S + s)*DK;
            o[cg]   = hsum2(acc[i][0]) * oscale;
            o[cg+8] = hsum2(acc[i][1]) * oscale;
        }
    }
}

// ============================================================
// Kernel 1b: maxQnorm[bh] = max_q ||Qhat[q]||. grid BH, 256 threads.
// ============================================================
__global__ void __launch_bounds__(256) qnorm_kernel() {
    __shared__ float red[256];
    const int bh = blockIdx.x, t = threadIdx.x;
    const float* Qb = g_Q + bh*S*DK;
    float mx = 0.f;
    for (int r = t; r < S; r += 256) {
        u64 a = 0;
        #pragma unroll
        for (int j = 0; j < 8; j++) {
            u64 q = ldg64(Qb + r*DK + 2*j);
            ffma2(a, q, q);
        }
        mx = fmaxf(mx, hsum2(a));
    }
    red[t] = mx;
    __syncthreads();
    #pragma unroll
    for (int s2 = 128; s2; s2 >>= 1) {
        if (t < s2) red[t] = fmaxf(red[t], red[t + s2]);
        __syncthreads();
    }
    if (t == 0) g_maxqn[bh] = sqrtf(red[0]);
}

// ============================================================
// Kernel 1c: prep fp16 operands + neg CS bias.
// grid BH*S/256, 256 threads, 1 row each.
//  QhT[bh][k][q] fp16 (coalesced across threads per k)
//  Kh[row][k] fp16 ; negb[row] = 8 - maxQn*||K[row]||
// ============================================================
__global__ void __launch_bounds__(256) prep_kernel() {
    const int row = blockIdx.x*256 + threadIdx.x;   // bh*S + i
    const int bh = row >> 11, i = row & (S-1);
    const float* Qr = g_Q + row*DK;
    #pragma unroll
    for (int k = 0; k < DK; k++)
        g_QhT[(bh*DK + k)*S + i] = __float2half(Qr[k]);

    const float* Kr = g_K + row*DK;
    float nrm = 0.f;
    __half2 kh[8];
    #pragma unroll
    for (int k = 0; k < 8; k++) {
        float2 v = unpk(ldg64(Kr + 2*k));
        nrm = fmaf(v.x, v.x, nrm);
        nrm = fmaf(v.y, v.y, nrm);
        kh[k] = __floats2half2_rn(v.x, v.y);
    }
    *reinterpret_cast<uint4*>(g_Kh + row*DK)     = *reinterpret_cast<uint4*>(&kh[0]);
    *reinterpret_cast<uint4*>(g_Kh + row*DK + 8) = *reinterpret_cast<uint4*>(&kh[4]);
    g_negb[row] = 8.0f - sqrtf(nrm) * g_maxqn[bh];
}

// ============================================================
// Kernel 2: scores via HMMA m16n8k16.  E[m][q] = 2^(s - b_m) fp16.
// grid (S/64, BH), 128 threads (4 warps, warp w owns q [q0+16w,+16)).
// A-frag: Qhat^T staged once, ldmatrix.x4.trans (validated R12 map).
// B-frag: K chunk staged in SMEM, u32 loads (validated R12 map).
// Neg CS bias rides in as the HMMA C-init (free). movmatrix flips
// output frags to [m][q] for coalesced-segment stores; 2-shuffle
// colsum partials per 8 m.
// ============================================================
__global__ void __launch_bounds__(128) scoresE_kernel() {
    __shared__ __align__(16) __half QhT[16][72];   // [k][q], 144B rows
    __shared__ __align__(16) __half Khs[128][16];  // [m][k], 32B rows
    __shared__ float bs[128];                      // negbias per m
    const int t = threadIdx.x, w = t >> 5, lane = t & 31;
    const int g = lane >> 2, tq = lane & 3;
    const int bh = blockIdx.y, q0 = blockIdx.x * 64;
    const __half* Kh = g_Kh + bh*S*DK;
    const float* nb = g_negb + bh*S;
    __half* Eb = g_E + (size_t)bh*S*S;
    float* cp = g_colpart + (blockIdx.x*4 + w)*(BH*S) + bh*S;

    // stage Qhat^T tile (16 k-rows x 64 q)
    {
        int r = t >> 3, c8 = t & 7;                // 128 threads = 16 x 8
        *reinterpret_cast<uint4*>(&QhT[r][c8*8]) =
            *reinterpret_cast<const uint4*>(g_QhT + (bh*DK + r)*S + q0 + c8*8);
    }
    __syncthreads();

    // A fragments once per CTA (validated trans-ldmatrix pattern)
    u32 qa0, qa1, qa2, qa3;
    {
        const int lrow = (lane & 7) + ((lane >> 4) << 3);
        const u32 addr = smem_u32(QhT) + lrow*144 + w*32 + ((lane >> 3) & 1)*16;
        asm volatile(
            "ldmatrix.sync.aligned.m8n8.x4.trans.shared.b16 {%0,%1,%2,%3}, [%4];"
            : "=r"(qa0), "=r"(qa1), "=r"(qa2), "=r"(qa3) : "r"(addr));
    }

    for (int m0 = 0; m0 < S; m0 += 128) {
        __syncthreads();                           // Khs/bs reuse
        *reinterpret_cast<uint4*>(&Khs[t][0]) =
            *reinterpret_cast<const uint4*>(Kh + (m0 + t)*DK);
        *reinterpret_cast<uint4*>(&Khs[t][8]) =
            *reinterpret_cast<const uint4*>(Kh + (m0 + t)*DK + 8);
        bs[t] = nb[m0 + t];
        __syncthreads();

        #pragma unroll 4
        for (int step = 0; step < 16; step++) {
            const int mk8 = step*8;
            // B fragments (validated map: n=g, k=2tq + {0,1,8,9})
            u32 b0 = *reinterpret_cast<const u32*>(&Khs[mk8 + g][2*tq]);
            u32 b1 = *reinterpret_cast<const u32*>(&Khs[mk8 + g][2*tq + 8]);
            float nb0 = bs[mk8 + 2*tq];
            float nb1 = bs[mk8 + 2*tq + 1];
            float c0, c1, c2, c3;
            asm volatile(
                "mma.sync.aligned.m16n8k16.row.col.f32.f16.f16.f32 "
                "{%0,%1,%2,%3}, {%4,%5,%6,%7}, {%8,%9}, {%10,%11,%10,%11};"
                : "=f"(c0), "=f"(c1), "=f"(c2), "=f"(c3)
                : "r"(qa0), "r"(qa1), "r"(qa2), "r"(qa3),
                  "r"(b0), "r"(b1), "f"(nb0), "f"(nb1));
            // exp2 (CS bound: results <= 2^8, no clamp needed)
            float e0 = ex2f(c0), e1 = ex2f(c1);
            float e2 = ex2f(c2), e3 = ex2f(c3);
            __half2 h0 = __floats2half2_rn(e0, e1);    // (q=g,    m=2tq/+1)
            __half2 h1 = __floats2half2_rn(e2, e3);    // (q=g+8,  m=2tq/+1)
            u32 t0, t1;
            asm("movmatrix.sync.aligned.m8n8.trans.b16 %0, %1;"
                : "=r"(t0) : "r"(*reinterpret_cast<u32*>(&h0)));
            asm("movmatrix.sync.aligned.m8n8.trans.b16 %0, %1;"
                : "=r"(t1) : "r"(*reinterpret_cast<u32*>(&h1)));
            // now t0 = (m=g, q=2tq/+1), t1 = same, q+8
            const int mg = m0 + mk8 + g;
            __half* Erow = Eb + (size_t)mg*S + q0 + w*16;
            *reinterpret_cast<u32*>(Erow + 2*tq)     = t0;
            *reinterpret_cast<u32*>(Erow + 2*tq + 8) = t1;
            // colsum partial over this warp's 16 q for m=g
            float2 f0 = __half22float2(*reinterpret_cast<__half2*>(&t0));
            float2 f1 = __half22float2(*reinterpret_cast<__half2*>(&t1));
            float ps = (f0.x + f0.y) + (f1.x + f1.y);
            ps += __shfl_xor_sync(0xffffffffu, ps, 1);
            ps += __shfl_xor_sync(0xffffffffu, ps, 2);
            if (tq == 0) cp[mg] = ps;
        }
    }
}

// ============================================================
// Kernel 2b: reduce 128 colsum sub-slabs -> Vp = V / colsum.
// grid BH*S/256, 256 threads, 1 m-row each (~40 MB traffic).
// ============================================================
__global__ void __launch_bounds__(256) colredVp_kernel() {
    const int row = blockIdx.x*256 + threadIdx.x;   // bh*S + m
    float s = 0.f;
    #pragma unroll 8
    for (int sl = 0; sl < NSL; sl++) s += g_colpart[sl*(BH*S) + row];
    const float rc = (s > 0.f) ? __frcp_rn(s) : 0.f;
    const float4* Vr = reinterpret_cast<const float4*>(g_V + row*DK);
    float4* Op = reinterpret_cast<float4*>(g_Vp + row*DK);
    #pragma unroll
    for (int v4 = 0; v4 < 4; v4++) {
        float4 v = Vr[v4];
        v.x *= rc; v.y *= rc; v.z *= rc; v.w *= rc;
        Op[v4] = v;
    }
}

// ============================================================
// Kernel 3: out[q,:] = sum_m E[m][q] * Vp[m,:]. R5/R9-proven scalar
// form: 128 threads, lane = q-pair, 4 warps split 128-m chunks,
// Vp broadcast from SMEM via LDS.128, scalar-store reduction.
// grid (S/64, BH). Measured 145us.
// ============================================================
__global__ void __launch_bounds__(128) ev_kernel() {
    __shared__ float Vs[128][16];
    __shared__ float red[3][64][18];
    const int t = threadIdx.x, w = t >> 5, lane = t & 31;
    const int bh = blockIdx.y;
    const int q0 = blockIdx.x * 64;
    const float* Vp = g_Vp + bh*S*DK;
    const __half* Eb = g_E + (size_t)bh*S*S;

    u64 acc0[8] = {}, acc1[8] = {};

    for (int m0 = 0; m0 < S; m0 += 128) {
        __syncthreads();
        #pragma unroll
        for (int i = 0; i < 4; i++) {
            int idx = t + i*128;
            int r = idx >> 2, c4 = idx & 3;
            *reinterpret_cast<float4*>(&Vs[r][c4*4]) =
                *reinterpret_cast<const float4*>(Vp + (m0 + r)*DK + c4*4);
        }
        __syncthreads();

        const int mbase = w * 32;
        #pragma unroll 4
        for (int mi = 0; mi < 32; mi++) {
            const int m  = mbase + mi;
            const int mg = m0 + m;
            __half2 eh = *reinterpret_cast<const __half2*>(
                Eb + (size_t)mg*S + q0 + 2*lane);      // coalesced 128B/warp
            float2 ef = __half22float2(eh);
            u64 E0 = dup2(ef.x), E1 = dup2(ef.y);
            const ulonglong2* vp = reinterpret_cast<const ulonglong2*>(&Vs[m][0]);
            #pragma unroll
            for (int p = 0; p < 4; p++) {
                ulonglong2 vv = vp[p];                 // LDS.128 broadcast
                ffma2(acc0[2*p],   E0, vv.x);
                ffma2(acc0[2*p+1], E0, vv.y);
                ffma2(acc1[2*p],   E1, vv.x);
                ffma2(acc1[2*p+1], E1, vv.y);
            }
        }
    }

    __syncthreads();
    if (w) {
        #pragma unroll
        for (int j = 0; j < 8; j++) {
            float2 p0 = unpk(acc0[j]), p1 = unpk(acc1[j]);
            red[w-1][2*lane][2*j]       = p0.x;
            red[w-1][2*lane][2*j+1]     = p0.y;
            red[w-1][2*lane+1][2*j]     = p1.x;
            red[w-1][2*lane+1][2*j+1]   = p1.y;
        }
    }
    __syncthreads();
    if (w == 0) {
        const int b = bh >> 3, h = bh & 7;
        float o0[16], o1[16];
        #pragma unroll
        for (int j = 0; j < 8; j++) {
            float2 p0 = unpk(acc0[j]), p1 = unpk(acc1[j]);
            o0[2*j] = p0.x; o0[2*j+1] = p0.y;
            o1[2*j] = p1.x; o1[2*j+1] = p1.y;
        }
        #pragma unroll
        for (int sl = 0; sl < 3; sl++)
            #pragma unroll
            for (int c = 0; c < 16; c++) {
                o0[c] += red[sl][2*lane][c];
                o1[c] += red[sl][2*lane+1][c];
            }
        float* d0 = g_head + (b*S + q0 + 2*lane)*D     + h*DK;
        float* d1 = g_head + (b*S + q0 + 2*lane + 1)*D + h*DK;
        #pragma unroll
        for (int c4 = 0; c4 < 4; c4++) {
            *reinterpret_cast<float4*>(d0 + c4*4) =
                make_float4(o0[c4*4], o0[c4*4+1], o0[c4*4+2], o0[c4*4+3]);
            *reinterpret_cast<float4*>(d1 + c4*4) =
                make_float4(o1[c4*4], o1[c4*4+1], o1[c4*4+2], o1[c4*4+3]);
        }
    }
}

// ============================================================
// Kernel 4: out = head[B*S,128] @ w_o[128,128]. grid 256, 256 thr.
// ============================================================
__global__ void final_proj_kernel(const float* __restrict__ wo,
                                  float* __restrict__ out) {
    __shared__ float hsT[128][34];
    const int t = threadIdx.x;
    const int row0 = blockIdx.x * 32;

    #pragma unroll
    for (int k = 0; k < 4; k++) {
        int idx = t + k*256;
        int r = idx >> 5, j4 = idx & 31;
        float4 v = *reinterpret_cast<const float4*>(g_head + (row0 + r)*D + j4*4);
        hsT[j4*4+0][r] = v.x; hsT[j4*4+1][r] = v.y;
        hsT[j4*4+2][r] = v.z; hsT[j4*4+3][r] = v.w;
    }
    __syncthreads();

    const int c = t & 127, rh = t >> 7;
    u64 acc[8] = {};
    #pragma unroll 4
    for (int j = 0; j < D; j++) {
        u64 w = dup2(wo[j*D + c]);
        #pragma unroll
        for (int p = 0; p < 8; p++)
            ffma2(acc[p], lds64(&hsT[j][rh*16 + 2*p]), w);
    }
    #pragma unroll
    for (int p = 0; p < 8; p++) {
        float2 v = unpk(acc[p]);
        int r = row0 + rh*16 + 2*p;
        out[r*D + c]     = v.x;
        out[(r+1)*D + c] = v.y;
    }
}

// ============================================================
extern "C" void kernel_launch(void* const* d_in, const int* in_sizes, int n_in,
                              void* d_out, int out_size) {
    const float* x  = (const float*)d_in[0];
    const float* wq = (const float*)d_in[1];
    const float* wk = (const float*)d_in[2];
    const float* wv = (const float*)d_in[3];
    const float* wo = (const float*)d_in[4];
    float* out = (float*)d_out;

    proj_kernel      <<< dim3(Bsz*S/64, 3), 128 >>>(x, wq, wk, wv);
    qnorm_kernel     <<< BH,                256 >>>();
    prep_kernel      <<< BH*S/256,          256 >>>();
    scoresE_kernel   <<< dim3(S/64, BH),    128 >>>();
    colredVp_kernel  <<< BH*S/256,          256 >>>();
    ev_kernel        <<< dim3(S/64, BH),    128 >>>();
    final_proj_kernel<<< Bsz*S/32,          256 >>>(wo, out);
}